// round 3
// baseline (speedup 1.0000x reference)
#include <cuda_runtime.h>

// Reference collapses: softmax(const) == uniform 1/N, so adj/a/e are dead code.
//   out[i,:] = relu( (colsum(h) @ W) / N )   -- one 64-float row broadcast 8192x.
// Single fused kernel: grid-wide sum -> 8-block reduce -> 1-block project -> broadcast.
// Grid sync via monotonic tickets (no reset needed across graph replays).

#define N_ROWSC 8192
#define F_INC   512
#define F_OUTC  64
#define GRID    512
#define THREADS 256
#define TOTAL_F4 (N_ROWSC * F_INC / 4)            // 1048576
#define STRIDE_F4 (GRID * THREADS)                // 131072
#define LOADS_PT (TOTAL_F4 / STRIDE_F4)           // 8  (exact)
#define N_RED   8
#define CG_PER_RED (128 / N_RED)                  // 16 column-groups (float4) per reducer

__device__ float4 g_partial[GRID * 128];          // per-block partial column sums (float4 layout)
__device__ float4 g_colsum[128];                  // reduced column sums (512 floats)
__device__ float  g_row[F_OUTC];                  // final broadcast row
__device__ unsigned long long g_cnt1;             // monotonic across launches
__device__ unsigned long long g_cnt2;             // monotonic across launches
__device__ volatile unsigned long long g_flag;    // epoch of completed row

__global__ __launch_bounds__(THREADS)
void gat_fused_kernel(const float4* __restrict__ h4,
                      const float*  __restrict__ W,
                      float4*       __restrict__ out)
{
    __shared__ float4 s4[THREADS];                 // 4KB, reused across phases
    __shared__ float4 srow[F_OUTC / 4];            // 256B
    __shared__ unsigned long long s_ticket;

    const int t = threadIdx.x;
    const int b = blockIdx.x;

    // ---- Phase A: partial column sums (fully coalesced, 8 indep float4 loads/thread) ----
    float4 acc = make_float4(0.f, 0.f, 0.f, 0.f);
    const int gid = b * THREADS + t;               // stride multiple of 128 -> col group = t & 127
    #pragma unroll
    for (int k = 0; k < LOADS_PT; ++k) {
        float4 v = h4[gid + k * STRIDE_F4];
        acc.x += v.x; acc.y += v.y; acc.z += v.z; acc.w += v.w;
    }
    s4[t] = acc;
    __syncthreads();
    if (t < 128) {
        float4 a0 = s4[t], a1 = s4[t + 128];       // both are column group t
        a0.x += a1.x; a0.y += a1.y; a0.z += a1.z; a0.w += a1.w;
        g_partial[b * 128 + t] = a0;               // indexed by blockIdx -> deterministic content
    }
    __threadfence();
    __syncthreads();

    if (t == 0) s_ticket = atomicAdd(&g_cnt1, 1ULL);
    __syncthreads();
    const unsigned long long ticket = s_ticket;
    const unsigned long long launch = ticket / GRID;         // epoch of this replay
    const unsigned long long want1  = (launch + 1) * GRID;
    const int r = (int)(ticket % GRID);

    // ---- Phase B1: last 8 arriving blocks reduce 16 column-groups each ----
    if (r >= GRID - N_RED) {
        if (t == 0) {
            while (atomicAdd(&g_cnt1, 0ULL) < want1) __nanosleep(32);
        }
        __syncthreads();

        const int j  = r - (GRID - N_RED);          // 0..7
        const int cg = j * CG_PER_RED + (t >> 4);   // this thread's column group
        const int m  = t & 15;                      // 16 lanes per column group
        float4 a = make_float4(0.f, 0.f, 0.f, 0.f);
        const int b0 = m * (GRID / 16);             // 32 contiguous blocks per lane
        #pragma unroll 4
        for (int bb = b0; bb < b0 + GRID / 16; ++bb) {
            float4 v = __ldcg(&g_partial[bb * 128 + cg]);
            a.x += v.x; a.y += v.y; a.z += v.z; a.w += v.w;
        }
        s4[t] = a;
        __syncthreads();
        if (m == 0) {                               // fixed combine order -> deterministic
            float4 tot = make_float4(0.f, 0.f, 0.f, 0.f);
            #pragma unroll
            for (int mm = 0; mm < 16; ++mm) {
                float4 v = s4[t + mm];
                tot.x += v.x; tot.y += v.y; tot.z += v.z; tot.w += v.w;
            }
            g_colsum[cg] = tot;
        }
        __threadfence();
        __syncthreads();

        if (t == 0) s_ticket = atomicAdd(&g_cnt2, 1ULL);
        __syncthreads();
        const unsigned long long t2 = s_ticket;

        // ---- Phase B2: 8th reducer projects colsum through W, writes g_row ----
        if (t2 % N_RED == N_RED - 1) {
            __syncthreads();                        // s4 reuse hazard guard
            float* sf = (float*)s4;                 // sf[0..511] = colsum, sf[512..767] = proj partials
            if (t < 128) {
                float4 v = __ldcg(&g_colsum[t]);
                sf[t * 4 + 0] = v.x; sf[t * 4 + 1] = v.y;
                sf[t * 4 + 2] = v.z; sf[t * 4 + 3] = v.w;
            }
            __syncthreads();
            const int col  = t & 63;
            const int half = t >> 6;                // 4 k-slices of 128
            float o = 0.f;
            #pragma unroll 8
            for (int i = 0; i < 128; ++i) {
                const int k = half * 128 + i;
                o = fmaf(sf[k], W[k * F_OUTC + col], o);   // coalesced W reads across threads
            }
            sf[512 + half * 64 + col] = o;
            __syncthreads();
            if (t < F_OUTC) {
                float v = (sf[512 + t] + sf[512 + 64 + t])
                        + (sf[512 + 128 + t] + sf[512 + 192 + t]);   // fixed order
                v *= (1.0f / (float)N_ROWSC);
                g_row[t] = fmaxf(v, 0.0f);
            }
            __threadfence();
            __syncthreads();
            if (t == 0) g_flag = launch + 1;        // release the row for this epoch
        }
    }

    // ---- Phase C: wait for row, broadcast to output (1 float4 store / thread) ----
    if (t == 0) {
        while (g_flag < launch + 1) __nanosleep(32);
    }
    __syncthreads();
    if (t < F_OUTC / 4) srow[t] = __ldcg(((const float4*)g_row) + t);
    __syncthreads();
    const int o = b * THREADS + t;                  // 0..131071 == N*F_OUT/4 exactly
    out[o] = srow[o & (F_OUTC / 4 - 1)];
}

extern "C" void kernel_launch(void* const* d_in, const int* in_sizes, int n_in,
                              void* d_out, int out_size) {
    (void)in_sizes; (void)n_in; (void)out_size;
    const float* h = (const float*)d_in[0];   // (8192, 512) fp32
    // d_in[1] = adj (8192,8192) -- dead code, never read
    const float* W = (const float*)d_in[2];   // (512, 64) fp32
    // d_in[3] = a (128,1)       -- dead code, never read
    float* out = (float*)d_out;               // (8192, 64) fp32

    gat_fused_kernel<<<GRID, THREADS>>>((const float4*)h, W, (float4*)out);
}

// round 4
// speedup vs baseline: 1.7225x; 1.7225x over previous
#include <cuda_runtime.h>

// Reference collapses: softmax(const(-9e15)) == uniform 1/N  =>  adj/a/e dead.
//   out[i,:] = relu( (colsum(h) @ W) / N )   -- one 64-float row broadcast 8192x.
// 3 kernels (graph nodes = free deterministic sync):
//   K1: partial column sums (16MB read, BW-bound) + W L2-prefetch overlap
//   K2: 1 block x 1024 thr: reduce partials + fully-parallel 512x64 projection
//   K3: broadcast 2MB

#define N_ROWSC 8192
#define F_INC   512
#define F_OUTC  64
#define GRID1   512
#define THR1    256
#define TOTAL_F4  (N_ROWSC * F_INC / 4)          // 1,048,576
#define STRIDE_F4 (GRID1 * THR1)                 // 131,072
#define LOADS_PT  (TOTAL_F4 / STRIDE_F4)         // 8 (exact)

__device__ float4 g_partial[GRID1 * 128];        // 1MB partial column sums
__device__ float  g_row[F_OUTC];                 // final broadcast row
__device__ float4 g_wsink[THR1];                 // prefetch sink (never read)

// ---- K1: partial column sums, fully coalesced, 8 indep float4 loads/thread ----
__global__ __launch_bounds__(THR1)
void k1_colsum(const float4* __restrict__ h4, const float4* __restrict__ W4) {
    __shared__ float4 s4[THR1];
    const int t = threadIdx.x, b = blockIdx.x;
    const int gid = b * THR1 + t;                // stride is mult of 128 -> colgrp = t&127
    float4 acc = make_float4(0.f, 0.f, 0.f, 0.f);
    #pragma unroll
    for (int k = 0; k < LOADS_PT; ++k) {
        float4 v = h4[gid + k * STRIDE_F4];
        acc.x += v.x; acc.y += v.y; acc.z += v.z; acc.w += v.w;
    }
    s4[t] = acc;
    __syncthreads();
    if (t < 128) {
        float4 a0 = s4[t], a1 = s4[t + 128];     // same column group
        a0.x += a1.x; a0.y += a1.y; a0.z += a1.z; a0.w += a1.w;
        g_partial[b * 128 + t] = a0;             // fixed layout -> deterministic
    }
    // Warm W (131KB = 8192 float4) into L2, overlapped with the 16MB read.
    if (b >= GRID1 - 32) {
        float4 w = __ldcg(&W4[(b - (GRID1 - 32)) * THR1 + t]);
        g_wsink[t] = w;                          // keeps the load alive; never read
    }
}

// ---- K2: single block, 1024 threads: reduce 1MB partials, project, relu ----
__global__ __launch_bounds__(1024)
void k2_reduce_project(const float* __restrict__ W) {
    __shared__ float4 r4[8 * 128];               // 16KB stage-1 partials
    __shared__ float  sf[F_INC];                 // colsum (512 floats)
    __shared__ float  pp[16 * F_OUTC];           // projection partials (4KB)
    const int t = threadIdx.x;

    // Stage 1: each thread sums 64 blocks for one column group (coalesced, L2).
    {
        const int cg = t & 127;                  // float4 column group
        const int w  = t >> 7;                   // 0..7 block-range slice
        float4 a = make_float4(0.f, 0.f, 0.f, 0.f);
        const int b0 = w * (GRID1 / 8);
        #pragma unroll 8
        for (int bb = b0; bb < b0 + GRID1 / 8; ++bb) {
            float4 v = __ldcg(&g_partial[bb * 128 + cg]);
            a.x += v.x; a.y += v.y; a.z += v.z; a.w += v.w;
        }
        r4[w * 128 + cg] = a;
    }
    __syncthreads();
    if (t < 128) {                               // fixed combine order
        float4 tot = make_float4(0.f, 0.f, 0.f, 0.f);
        #pragma unroll
        for (int w = 0; w < 8; ++w) {
            float4 v = r4[w * 128 + t];
            tot.x += v.x; tot.y += v.y; tot.z += v.z; tot.w += v.w;
        }
        sf[t * 4 + 0] = tot.x; sf[t * 4 + 1] = tot.y;
        sf[t * 4 + 2] = tot.z; sf[t * 4 + 3] = tot.w;
    }
    __syncthreads();

    // Stage 2: projection with ALL 1024 threads: col = t&63, 16 k-slices of 32.
    {
        const int col = t & 63;
        const int sl  = t >> 6;                  // 0..15
        float o = 0.f;
        #pragma unroll 8
        for (int i = 0; i < 32; ++i) {
            const int k = sl * 32 + i;
            o = fmaf(sf[k], W[k * F_OUTC + col], o);  // W L2-warm, coalesced
        }
        pp[sl * F_OUTC + col] = o;
    }
    __syncthreads();
    if (t < F_OUTC) {                            // fixed combine order
        float v = 0.f;
        #pragma unroll
        for (int sl = 0; sl < 16; ++sl) v += pp[sl * F_OUTC + t];
        v *= (1.0f / (float)N_ROWSC);
        g_row[t] = fmaxf(v, 0.0f);
    }
}

// ---- K3: broadcast 64-float row to 8192 rows (1 float4 store / thread) ----
__global__ __launch_bounds__(256)
void k3_broadcast(float4* __restrict__ out) {
    __shared__ float4 rowv[F_OUTC / 4];
    if (threadIdx.x < F_OUTC / 4)
        rowv[threadIdx.x] = reinterpret_cast<const float4*>(g_row)[threadIdx.x];
    __syncthreads();
    const int i = blockIdx.x * blockDim.x + threadIdx.x;   // 0..131071 exact
    out[i] = rowv[i & (F_OUTC / 4 - 1)];
}

extern "C" void kernel_launch(void* const* d_in, const int* in_sizes, int n_in,
                              void* d_out, int out_size) {
    (void)in_sizes; (void)n_in; (void)out_size;
    const float* h = (const float*)d_in[0];   // (8192, 512) fp32
    // d_in[1] = adj (8192,8192) -- dead code, never read
    const float* W = (const float*)d_in[2];   // (512, 64) fp32
    // d_in[3] = a (128,1)       -- dead code, never read
    float* out = (float*)d_out;               // (8192, 64) fp32

    k1_colsum<<<GRID1, THR1>>>((const float4*)h, (const float4*)W);
    k2_reduce_project<<<1, 1024>>>(W);
    k3_broadcast<<<(N_ROWSC * F_OUTC / 4) / 256, 256>>>((float4*)out);
}

// round 5
// speedup vs baseline: 2.5504x; 1.4806x over previous
#include <cuda_runtime.h>

// Reference collapses: softmax(const(-9e15)) == uniform 1/N  =>  adj/a/e dead.
//   out[i,:] = relu( (colsum(h) @ W) / N )  -- one 64-float row broadcast 8192x.
// Single fused kernel, ONE sync point:
//   phase A: grid-wide partial column sums (16MB coalesced read) + W L2-prefetch
//   last-arriving block (ticket): reduce partials + project + relu -> g_row, set flag
//   all blocks: spin on flag (plain volatile read, no atomics), broadcast 2MB out.

#define N_ROWSC 8192
#define F_INC   512
#define F_OUTC  64
#define GRID    128
#define THREADS 1024
#define TOTAL_F4  (N_ROWSC * F_INC / 4)          // 1,048,576
#define STRIDE_F4 (GRID * THREADS)               // 131,072
#define LOADS_PT  (TOTAL_F4 / STRIDE_F4)         // 8 (exact)

__device__ float4 g_partial[GRID * 128];          // 256 KB partial column sums
__device__ float  g_row[F_OUTC];                  // final broadcast row
__device__ unsigned long long g_cnt;              // monotonic block-arrival counter
__device__ volatile unsigned long long g_flag;    // epoch of completed row

__global__ __launch_bounds__(THREADS)
void gat_one_kernel(const float4* __restrict__ h4,
                    const float*  __restrict__ W,
                    const float4* __restrict__ W4,
                    float4*       __restrict__ out)
{
    __shared__ float4 s4[THREADS];                // 16 KB, reused
    __shared__ float  sf[F_INC];                  // 2 KB colsum
    __shared__ float  pp[16 * F_OUTC];            // 4 KB projection partials
    __shared__ float4 srow[F_OUTC / 4];           // 256 B
    __shared__ unsigned long long s_ticket;

    const int t = threadIdx.x;
    const int b = blockIdx.x;

    // W prefetch into L2 (blocks 0..31 cover 32768 float4 = all of W), kept
    // alive by an asm sink -- no extra stores, overlaps with phase A reads.
    if (b < 32) {
        float4 w = __ldcg(&W4[b * THREADS + t]);
        asm volatile("" :: "f"(w.x), "f"(w.y), "f"(w.z), "f"(w.w));
    }

    // ---- Phase A: partial column sums (coalesced, 8 indep float4 loads/thread) ----
    {
        const int gid = b * THREADS + t;          // stride mult of 128 -> colgrp = t & 127
        float4 acc = make_float4(0.f, 0.f, 0.f, 0.f);
        #pragma unroll
        for (int k = 0; k < LOADS_PT; ++k) {
            float4 v = h4[gid + k * STRIDE_F4];
            acc.x += v.x; acc.y += v.y; acc.z += v.z; acc.w += v.w;
        }
        s4[t] = acc;
    }
    __syncthreads();
    if (t < 128) {                                // fixed order -> deterministic
        float4 a = s4[t];
        #pragma unroll
        for (int j = 1; j < 8; ++j) {
            float4 v = s4[t + 128 * j];           // same column group t
            a.x += v.x; a.y += v.y; a.z += v.z; a.w += v.w;
        }
        g_partial[b * 128 + t] = a;
    }
    __threadfence();
    __syncthreads();

    if (t == 0) s_ticket = atomicAdd(&g_cnt, 1ULL);
    __syncthreads();
    const unsigned long long ticket = s_ticket;
    const unsigned long long launch = ticket / GRID;   // this replay's epoch

    if (ticket % GRID == GRID - 1) {
        // ---- Reducer (last arrival: all partials are fenced & visible) ----
        {
            const int cg = t & 127;               // column group
            const int w  = t >> 7;                // 0..7 block-range slice
            float4 a = make_float4(0.f, 0.f, 0.f, 0.f);
            const int b0 = w * (GRID / 8);
            #pragma unroll
            for (int bb = b0; bb < b0 + GRID / 8; ++bb) {   // 16 L2 loads
                float4 v = __ldcg(&g_partial[bb * 128 + cg]);
                a.x += v.x; a.y += v.y; a.z += v.z; a.w += v.w;
            }
            s4[w * 128 + cg] = a;
        }
        __syncthreads();
        if (t < 128) {                            // fixed combine order
            float4 tot = make_float4(0.f, 0.f, 0.f, 0.f);
            #pragma unroll
            for (int w = 0; w < 8; ++w) {
                float4 v = s4[w * 128 + t];
                tot.x += v.x; tot.y += v.y; tot.z += v.z; tot.w += v.w;
            }
            sf[t * 4 + 0] = tot.x; sf[t * 4 + 1] = tot.y;
            sf[t * 4 + 2] = tot.z; sf[t * 4 + 3] = tot.w;
        }
        __syncthreads();

        // Projection with all 1024 threads: col = t&63, 16 k-slices of 32.
        {
            const int col = t & 63;
            const int sl  = t >> 6;               // 0..15
            float o = 0.f;
            #pragma unroll 8
            for (int i = 0; i < 32; ++i) {
                const int k = sl * 32 + i;
                o = fmaf(sf[k], W[k * F_OUTC + col], o);   // W is L2-warm
            }
            pp[sl * F_OUTC + col] = o;
        }
        __syncthreads();
        if (t < F_OUTC) {                         // fixed combine order
            float v = 0.f;
            #pragma unroll
            for (int sl = 0; sl < 16; ++sl) v += pp[sl * F_OUTC + t];
            v *= (1.0f / (float)N_ROWSC);
            g_row[t] = fmaxf(v, 0.0f);
        }
        __threadfence();
        __syncthreads();
        if (t == 0) g_flag = launch + 1;          // release (fence above = release)
    } else {
        // ---- Waiters: single plain-load spin (no atomic RMW contention) ----
        if (t == 0) {
            while (g_flag < launch + 1) __nanosleep(64);
            __threadfence();                      // acquire
        }
        __syncthreads();
    }

    // ---- Broadcast: each block writes its exact 4 KB slice (1 float4/thread) ----
    if (t < F_OUTC / 4) srow[t] = __ldcg(((const float4*)g_row) + t);
    __syncthreads();
    const int o = b * THREADS + t;                // 0..131071 == N*F_OUT/4 exactly
    out[o] = srow[o & (F_OUTC / 4 - 1)];
}

extern "C" void kernel_launch(void* const* d_in, const int* in_sizes, int n_in,
                              void* d_out, int out_size) {
    (void)in_sizes; (void)n_in; (void)out_size;
    const float* h = (const float*)d_in[0];   // (8192, 512) fp32
    // d_in[1] = adj (8192,8192) -- dead code, never read
    const float* W = (const float*)d_in[2];   // (512, 64) fp32
    // d_in[3] = a (128,1)       -- dead code, never read
    float* out = (float*)d_out;               // (8192, 64) fp32

    gat_one_kernel<<<GRID, THREADS>>>((const float4*)h, W, (const float4*)W,
                                      (float4*)out);
}